// round 12
// baseline (speedup 1.0000x reference)
#include <cuda_runtime.h>

#define THREADS  256
#define WPB      8          // warps per block
#define RPW      2          // rows per warp, fully front-issued
#define RPB      (WPB * RPW)
#define NTERMS   16
#define NBUCKETS 64
#define ROWF     512        // floats per row
#define ROWB     2048       // bytes per row

// Buckets padded to one 128-B L2 line each: [b][0]=sum, [b][1]=cnt.
// Zero at module load; finalizing block restores zeros each launch.
__device__ double   g_acc[NBUCKETS][16];
__device__ unsigned g_ticket;

// C = 255*ln2 + lgamma(256) - 256*ln(2*pi)
#define LOSS_C 867.968103160394f

__device__ __forceinline__ float dot4(float4 a, float4 b) {
    return a.x*b.x + a.y*b.y + a.z*b.z + a.w*b.w;
}
__device__ __forceinline__ unsigned su32(const void* p) {
    return (unsigned)__cvta_generic_to_shared(p);
}
__device__ __forceinline__ void cp16(unsigned dst, const void* src) {
    asm volatile("cp.async.cg.shared.global [%0], [%1], 16;"
                 :: "r"(dst), "l"(src) : "memory");
}
__device__ __forceinline__ void red_add_release_f64(double* p, double v) {
    asm volatile("red.add.release.gpu.global.f64 [%0], %1;"
                 :: "l"(p), "d"(v) : "memory");
}
__device__ __forceinline__ unsigned atom_add_acqrel_u32(unsigned* p, unsigned v) {
    unsigned r;
    asm volatile("atom.add.acq_rel.gpu.global.u32 %0, [%1], %2;"
                 : "=r"(r) : "l"(p), "r"(v) : "memory");
    return r;
}
__device__ __forceinline__ double ld_cg_f64(const double* p) {
    double r;
    asm volatile("ld.global.cg.f64 %0, [%1];" : "=d"(r) : "l"(p) : "memory");
    return r;
}
__device__ __forceinline__ void st_cg_f64(double* p, double v) {
    asm volatile("st.global.cg.f64 [%0], %1;" :: "l"(p), "d"(v) : "memory");
}

__global__ void __launch_bounds__(THREADS)
nll_main(const float* __restrict__ preds,
         const void*  __restrict__ target,
         const float* __restrict__ emb,
         float* __restrict__ out, int out_size, int n, long long vocab)
{
    __shared__ alignas(16) float s_emb[RPB * ROWF];   // 32 KB
    __shared__ float    sh_loss[WPB], sh_cnt[WPB];
    __shared__ unsigned s_tkt;

    int tid  = threadIdx.x;
    int lane = tid & 31;
    int w    = tid >> 5;
    int row0 = blockIdx.x * RPB + w * RPW;

    // ---- inline dtype detection: every warp reads the SAME first 32 int64
    // words (256 B, L2-broadcast; in-bounds for both layouts when n >= 64).
    // int64 buffer: all in [0,vocab) -> flag 0. int32 buffer: word i valid
    // only if tgt[2i+1]==0 (p~2e-5); all-32-valid is impossible.
    long long dv = ((const long long*)target)[lane];
    unsigned badm = __ballot_sync(0xffffffffu, dv < 0 || dv >= vocab);
    int flag32 = (badm != 0);

    // ---- both targets in ONE parallel hop (lanes 0..RPW-1) ----
    long long t_l = 1;
    if (lane < RPW) {
        int r = row0 + lane;
        if (r < n) {
            t_l = flag32 ? (long long)((const int*)target)[r]
                         : ((const long long*)target)[r];
        }
    }

    // ---- preds for both rows: 8 independent LDG.128/lane, in flight now ----
    int r0c = row0     < n ? row0     : 0;
    int r1c = row0 + 1 < n ? row0 + 1 : 0;
    const float4* p0 = reinterpret_cast<const float4*>(preds) + (size_t)r0c * ROWF/4 + lane;
    const float4* p1 = reinterpret_cast<const float4*>(preds) + (size_t)r1c * ROWF/4 + lane;
    float4 a0 = p0[0], a1 = p0[32], a2 = p0[64], a3 = p0[96];
    float4 c0 = p1[0], c1 = p1[32], c2 = p1[64], c3 = p1[96];

    long long t0 = __shfl_sync(0xffffffffu, t_l, 0);
    long long t1 = __shfl_sync(0xffffffffu, t_l, 1);
    if (row0     >= n) t0 = 1;           // PAD => contributes nothing
    if (row0 + 1 >= n) t1 = 1;

    // ---- both emb gathers issued back-to-back, ONE wait ----
    // Lane copies chunks lane+32k of each row and consumes exactly those.
    const char* ge0 = (const char*)(emb + (size_t)t0 * ROWF);
    const char* ge1 = (const char*)(emb + (size_t)t1 * ROWF);
    unsigned se0 = su32(s_emb) + (unsigned)(w * RPW)     * ROWB;
    unsigned se1 = su32(s_emb) + (unsigned)(w * RPW + 1) * ROWB;
    #pragma unroll
    for (int k = 0; k < 4; k++) {
        unsigned c = (unsigned)lane + 32u * k;
        cp16(se0 + c * 16u, ge0 + (size_t)c * 16u);
    }
    #pragma unroll
    for (int k = 0; k < 4; k++) {
        unsigned c = (unsigned)lane + 32u * k;
        cp16(se1 + c * 16u, ge1 + (size_t)c * 16u);
    }
    asm volatile("cp.async.commit_group;" ::: "memory");
    asm volatile("cp.async.wait_group 0;" ::: "memory");

    const float4* e0 = reinterpret_cast<const float4*>(s_emb) + (w * RPW)     * (ROWF/4) + lane;
    const float4* e1 = reinterpret_cast<const float4*>(s_emb) + (w * RPW + 1) * (ROWF/4) + lane;
    float4 b0 = e0[0], b1 = e0[32], b2 = e0[64], b3 = e0[96];
    float4 d0 = e1[0], d1 = e1[32], d2 = e1[64], d3 = e1[96];

    float ss0 = dot4(a0,a0) + dot4(a1,a1) + dot4(a2,a2) + dot4(a3,a3);
    float dt0 = dot4(a0,b0) + dot4(a1,b1) + dot4(a2,b2) + dot4(a3,b3);
    float ss1 = dot4(c0,c0) + dot4(c1,c1) + dot4(c2,c2) + dot4(c3,c3);
    float dt1 = dot4(c0,d0) + dot4(c1,d1) + dot4(c2,d2) + dot4(c3,d3);

    #pragma unroll
    for (int o = 16; o > 0; o >>= 1) {
        ss0 += __shfl_down_sync(0xffffffffu, ss0, o);
        dt0 += __shfl_down_sync(0xffffffffu, dt0, o);
        ss1 += __shfl_down_sync(0xffffffffu, ss1, o);
        dt1 += __shfl_down_sync(0xffffffffu, dt1, o);
    }

    float loss = 0.0f, cnt = 0.0f;
    if (lane == 0) {
        #pragma unroll
        for (int r = 0; r < RPW; r++) {
            long long t = r == 0 ? t0 : t1;
            float ss    = r == 0 ? ss0 : ss1;
            float dt    = r == 0 ? dt0 : dt1;
            if (t != 1) {   // PAD_ID == 1
                float z = sqrtf(ss);
                float x = 0.25f * ss;
                // S = sum_j x^j/(j!*(256)_j); x~128 => converged before j=16.
                float S = 1.0f, term = 1.0f;
                #pragma unroll
                for (int j = 1; j < NTERMS; j++) {
                    term *= x * (1.0f / ((float)j * (255.0f + (float)j)));
                    S += term;
                }
                loss += logf(S) - z - dt - LOSS_C;
                cnt  += 1.0f;
            }
        }
        sh_loss[w] = loss; sh_cnt[w] = cnt;
    }
    __syncthreads();

    // ---- block reduce: 2 global reds + 1 ticket per block ----
    if (tid == 0) {
        float L = 0.0f, C = 0.0f;
        #pragma unroll
        for (int i = 0; i < WPB; i++) { L += sh_loss[i]; C += sh_cnt[i]; }
        int b = blockIdx.x & (NBUCKETS - 1);
        red_add_release_f64(&g_acc[b][0], (double)L);
        red_add_release_f64(&g_acc[b][1], (double)C);
        s_tkt = atom_add_acqrel_u32(&g_ticket, 1u);
    }
    __syncthreads();

    // ---- last block finalizes + resets state ----
    if (s_tkt == gridDim.x - 1) {
        double s = 0.0, c = 0.0;
        if (tid < NBUCKETS) {
            s = ld_cg_f64(&g_acc[tid][0]);
            c = ld_cg_f64(&g_acc[tid][1]);
        }
        #pragma unroll
        for (int o = 16; o > 0; o >>= 1) {
            s += __shfl_down_sync(0xffffffffu, s, o);
            c += __shfl_down_sync(0xffffffffu, c, o);
        }
        __shared__ double sh_s[2], sh_c[2];
        if (tid < NBUCKETS && lane == 0) { sh_s[tid >> 5] = s; sh_c[tid >> 5] = c; }
        __syncthreads();
        if (tid == 0) {
            float r = (float)((sh_s[0] + sh_s[1]) / (sh_c[0] + sh_c[1]));
            for (int i = 0; i < out_size; i++) out[i] = r;
            g_ticket = 0u;
        }
        if (tid < NBUCKETS) {
            st_cg_f64(&g_acc[tid][0], 0.0);
            st_cg_f64(&g_acc[tid][1], 0.0);
        }
    }
}

extern "C" void kernel_launch(void* const* d_in, const int* in_sizes, int n_in,
                              void* d_out, int out_size) {
    const float* preds  = (const float*)d_in[0];
    const void*  target = d_in[1];
    const float* emb    = (const float*)d_in[2];
    int n = in_sizes[1];                              // B*S rows
    long long vocab = (long long)(in_sizes[2] / 512); // rows of emb table

    int blocks = (n + RPB - 1) / RPB;
    nll_main<<<blocks, THREADS>>>(preds, target, emb, (float*)d_out,
                                  out_size, n, vocab);
}